// round 16
// baseline (speedup 1.0000x reference)
#include <cuda_runtime.h>
#include <cuda_bf16.h>
#include <math.h>

typedef unsigned int u32;

#define BT   64
#define NCTA 128
#define NTHR 512
#define TH   20
#define LP   30
#define DTC  0.1f
#define D2C  0.005f
#define PADK 72     // bf16 per row in W/X tiles (conflict-free frag loads)
#define CPAD 33     // c2f row pad

struct __align__(16) SM {
    __nv_bfloat16 Wt[3][2][128 * PADK];  // [layer][hi/lo][m][k] k=[x32|h32]
    __nv_bfloat16 Xt[3][2][64 * PADK];   // [layer][hi/lo][n][k] x cols 0-31, h cols 32-63
    float c2f[64][CPAD];                 // layer-2 c, [n][d]
    float XP[24][64];
    float Zs[2][TH][64];
    float bsum[3][128];
    float WinT[24][32];
    float Winb[32];
    float WoutT[32][4];
    float Woutb[4];
};

__device__ __forceinline__ void barg(int g) {   // per-group barrier: 128 threads
    asm volatile("bar.sync %0, %1;" :: "r"(g + 1), "r"(128) : "memory");
}
__device__ __forceinline__ float tanha(float x) {
    float y; asm("tanh.approx.f32 %0, %1;" : "=f"(y) : "f"(x)); return y;
}
__device__ __forceinline__ float sigm(float z) { return fmaf(tanha(0.5f * z), 0.5f, 0.5f); }
__device__ __forceinline__ u32 pkbf(float lo, float hi) {
    u32 r; asm("cvt.rn.bf16x2.f32 %0, %1, %2;" : "=r"(r) : "f"(hi), "f"(lo)); return r;
}
__device__ __forceinline__ void mma16816(float* d, const u32* a, u32 b0, u32 b1) {
    asm volatile("mma.sync.aligned.m16n8k16.row.col.f32.bf16.bf16.f32 "
        "{%0,%1,%2,%3}, {%4,%5,%6,%7}, {%8,%9}, {%0,%1,%2,%3};"
        : "+f"(d[0]), "+f"(d[1]), "+f"(d[2]), "+f"(d[3])
        : "r"(a[0]), "r"(a[1]), "r"(a[2]), "r"(a[3]), "r"(b0), "r"(b1));
}

__device__ __forceinline__ void pack_wts(SM& s, int tid,
        const float* __restrict__ Wih, const float* __restrict__ Whh,
        const float* __restrict__ bih, const float* __restrict__ bhh) {
    for (int i = tid; i < 3 * 128 * 64; i += NTHR) {
        int l = i >> 13, r = i & 8191, m = r >> 6, k = r & 63;
        float v = (k < 32) ? Wih[l * 4096 + m * 32 + k] : Whh[l * 4096 + m * 32 + (k - 32)];
        __nv_bfloat16 h = __float2bfloat16(v);
        s.Wt[l][0][m * PADK + k] = h;
        s.Wt[l][1][m * PADK + k] = __float2bfloat16(v - __bfloat162float(h));
    }
    for (int i = tid; i < 384; i += NTHR)
        ((float*)s.bsum)[i] = bih[i] + bhh[i];
}

__device__ __forceinline__ void kpred_f(float X[3], float P[9], float g0, float g1, float g2) {
    X[0] = X[0] + DTC * X[1] + D2C * X[2];
    X[1] = X[1] + DTC * X[2];
    float A[9];
#pragma unroll
    for (int j = 0; j < 3; j++) {
        A[0 * 3 + j] = P[0 * 3 + j] + DTC * P[1 * 3 + j] + D2C * P[2 * 3 + j];
        A[1 * 3 + j] = P[1 * 3 + j] + DTC * P[2 * 3 + j];
        A[2 * 3 + j] = P[2 * 3 + j];
    }
#pragma unroll
    for (int i = 0; i < 3; i++) {
        float qi = (i == 0) ? g0 : ((i == 1) ? g1 : g2);
        P[i * 3 + 0] = A[i * 3 + 0] + DTC * A[i * 3 + 1] + D2C * A[i * 3 + 2] + qi * g0;
        P[i * 3 + 1] = A[i * 3 + 1] + DTC * A[i * 3 + 2] + qi * g1;
        P[i * 3 + 2] = A[i * 3 + 2] + qi * g2;
    }
}
__device__ __forceinline__ void kupd_f(float X[3], float P[9], float z, float R) {
    float y = z - X[0];
    float S = P[0] + R;
    float inv = 1.0f / S;
    float K0 = P[0] * inv, K1 = P[3] * inv, K2 = P[6] * inv;
    X[0] += y * K0; X[1] += y * K1; X[2] += y * K2;
    float r0 = P[0], r1 = P[1], r2 = P[2];
    P[0] -= K0 * r0; P[1] -= K0 * r1; P[2] -= K0 * r2;
    P[3] -= K1 * r0; P[4] -= K1 * r1; P[5] -= K1 * r2;
    P[6] -= K2 * r0; P[7] -= K2 * r1; P[8] -= K2 * r2;
}

// input layer: thread does 4 d-values for one batch col -> Xt[0] x-cols
__device__ __forceinline__ void input_layer(SM& s, int b, int d0) {
    float acc[4];
    *(float4*)&acc[0] = *(const float4*)&s.Winb[d0];
#pragma unroll
    for (int k = 0; k < 24; k++) {
        float xv = s.XP[k][b];
        float4 w = *(const float4*)&s.WinT[k][d0];
        acc[0] = fmaf(w.x, xv, acc[0]); acc[1] = fmaf(w.y, xv, acc[1]);
        acc[2] = fmaf(w.z, xv, acc[2]); acc[3] = fmaf(w.w, xv, acc[3]);
    }
    float xh[4], xl[4];
#pragma unroll
    for (int j = 0; j < 4; j++) {
        float x = tanha(acc[j]);
        float h = __bfloat162float(__float2bfloat16(x));
        xh[j] = h; xl[j] = x - h;
    }
    uint2 qh, ql;
    qh.x = pkbf(xh[0], xh[1]); qh.y = pkbf(xh[2], xh[3]);
    ql.x = pkbf(xl[0], xl[1]); ql.y = pkbf(xl[2], xl[3]);
    *(uint2*)&s.Xt[0][0][b * PADK + d0] = qh;
    *(uint2*)&s.Xt[0][1][b * PADK + d0] = ql;
}

// half-K GEMM into D[gi][4]: kh=0 -> x cols, kh=1 -> h cols.
// Warp: 4 gate tiles for d-slice (w0&1)*16, n-tile grp*16+(w0>>1)*8.
__device__ __forceinline__ void mma_part(SM& s, int l, int kh, int w0, int lane, int grp,
                                         float (&D)[4][4], bool zero)
{
    const int g8 = lane >> 2, tg = lane & 3;
    const int d0 = (w0 & 1) * 16;
    const int nb = grp * 16 + (w0 >> 1) * 8;
    if (zero) {
#pragma unroll
        for (int gi = 0; gi < 4; gi++)
#pragma unroll
            for (int j = 0; j < 4; j++) D[gi][j] = 0.f;
    }
    const __nv_bfloat16* __restrict__ W0 = &s.Wt[l][0][0];
    const __nv_bfloat16* __restrict__ W1 = &s.Wt[l][1][0];
    const __nv_bfloat16* __restrict__ X0 = &s.Xt[l][0][0];
    const __nv_bfloat16* __restrict__ X1 = &s.Xt[l][1][0];
#pragma unroll
    for (int kk = 0; kk < 2; kk++) {
        const int k0 = (kh * 2 + kk) * 16 + 2 * tg;
        const int n = nb + g8;
        u32 bh0 = *(const u32*)&X0[n * PADK + k0];
        u32 bh1 = *(const u32*)&X0[n * PADK + k0 + 8];
        u32 bl0 = *(const u32*)&X1[n * PADK + k0];
        u32 bl1 = *(const u32*)&X1[n * PADK + k0 + 8];
#pragma unroll
        for (int gi = 0; gi < 4; gi++) {
            const int m = gi * 32 + d0 + g8;
            u32 ah[4], al[4];
            ah[0] = *(const u32*)&W0[m * PADK + k0];
            ah[1] = *(const u32*)&W0[(m + 8) * PADK + k0];
            ah[2] = *(const u32*)&W0[m * PADK + k0 + 8];
            ah[3] = *(const u32*)&W0[(m + 8) * PADK + k0 + 8];
            al[0] = *(const u32*)&W1[m * PADK + k0];
            al[1] = *(const u32*)&W1[(m + 8) * PADK + k0];
            al[2] = *(const u32*)&W1[m * PADK + k0 + 8];
            al[3] = *(const u32*)&W1[(m + 8) * PADK + k0 + 8];
            mma16816(D[gi], ah, bh0, bh1);
            mma16816(D[gi], ah, bl0, bl1);
            mma16816(D[gi], al, bh0, bh1);
        }
    }
}

// in-register epilogue: gates in D -> c,h -> bf16 hi/lo tiles (+ c2f for l==2)
__device__ __forceinline__ void epilogue(SM& s, int l, int w0, int lane, int grp,
                                         float (&D)[4][4], float* C)
{
    const int g8 = lane >> 2, tg = lane & 3;
    const int d0 = (w0 & 1) * 16;
    const int nb = grp * 16 + (w0 >> 1) * 8;
    const float* bb = &s.bsum[l][0];
    __nv_bfloat16* __restrict__ H0 = &s.Xt[l][0][0];
    __nv_bfloat16* __restrict__ H1 = &s.Xt[l][1][0];
#pragma unroll
    for (int dd = 0; dd < 2; dd++) {
        const int d = d0 + g8 + dd * 8;
        const float bi = bb[d], bf_ = bb[32 + d], bg = bb[64 + d], bo = bb[96 + d];
#pragma unroll
        for (int dn = 0; dn < 2; dn++) {
            const int j = dd * 2 + dn;
            const int n = nb + 2 * tg + dn;
            const int ci = dd * 2 + dn;
            float c = fmaf(sigm(D[1][j] + bf_), C[ci],
                           sigm(D[0][j] + bi) * tanha(D[2][j] + bg));
            float h = sigm(D[3][j] + bo) * tanha(c);
            C[ci] = c;
            __nv_bfloat16 hh = __float2bfloat16(h);
            H0[n * PADK + 32 + d] = hh;
            H1[n * PADK + 32 + d] = __float2bfloat16(h - __bfloat162float(hh));
            if (l < 2) {
                __nv_bfloat16 ch = __float2bfloat16(c);
                s.Xt[l + 1][0][n * PADK + d] = ch;
                s.Xt[l + 1][1][n * PADK + d] = __float2bfloat16(c - __bfloat162float(ch));
            } else {
                s.c2f[n][d] = c;
            }
        }
    }
}

__global__ void __launch_bounds__(NTHR, 1)
kalman_lstm_kernel(const float* __restrict__ hist,
                   const float* __restrict__ mx,  const float* __restrict__ my,
                   const float* __restrict__ vsx, const float* __restrict__ asx,
                   const float* __restrict__ Rxp, const float* __restrict__ Ryp,
                   const float* __restrict__ Gx,  const float* __restrict__ Gy,
                   const float* __restrict__ WinW, const float* __restrict__ Winb,
                   const float* __restrict__ eWih, const float* __restrict__ eWhh,
                   const float* __restrict__ ebih, const float* __restrict__ ebhh,
                   const float* __restrict__ dWih, const float* __restrict__ dWhh,
                   const float* __restrict__ dbih, const float* __restrict__ dbhh,
                   const float* __restrict__ WoutW, const float* __restrict__ Woutb,
                   float* __restrict__ out)
{
    extern __shared__ char smraw[];
    SM& s = *reinterpret_cast<SM*>(smraw);
    const int tid  = threadIdx.x;
    const int wid  = tid >> 5, lane = tid & 31;
    const int b0   = blockIdx.x * BT;
    const int grp  = wid >> 2;                 // 4 groups x 16 batch
    const int w0   = wid & 3;
    const int ltid = tid & 127;
    const int b    = grp * 16 + (ltid & 15);   // batch col for input layer
    const int d0o  = (ltid >> 4) * 4;          // 4-wide d slice for input layer

    // ---- one-time setup (full CTA) ----
    pack_wts(s, tid, eWih, eWhh, ebih, ebhh);
    for (int i = tid; i < 24 * 32; i += NTHR) {
        int d = i & 31, k = i >> 5;
        s.WinT[k][d] = WinW[d * 24 + k];
    }
    if (tid < 32) s.Winb[tid] = Winb[tid];
    if (tid < 128) { int k = tid >> 2, qq = tid & 3; s.WoutT[k][qq] = WoutW[qq * 32 + k]; }
    if (tid < 4)  s.Woutb[tid] = Woutb[tid];
    for (int i = tid; i < BT * 40; i += NTHR) {
        int bb2 = i / 40, j = i % 40;
        s.Zs[j & 1][j >> 1][bb2] = hist[(size_t)(b0 + bb2) * 40 + j];
    }
    for (int i = tid; i < (int)(sizeof(s.Xt) / 4); i += NTHR)
        ((u32*)&s.Xt[0][0][0])[i] = 0u;

    const float rx = Rxp[0] * Rxp[0], ry = Ryp[0] * Ryp[0];
    const float vv = vsx[0] * vsx[0], aa = asx[0] * asx[0];
    const float gxe0 = Gx[0] * mx[0], gxe1 = Gx[1] * mx[0], gxe2 = Gx[2] * mx[0];
    const float gye0 = Gy[0] * my[0], gye1 = Gy[1] * my[0], gye2 = Gy[2] * my[0];
    const float gx0 = Gx[0], gx1 = Gx[1], gx2 = Gx[2];
    const float gy0 = Gy[0], gy1 = Gy[1], gy2 = Gy[2];

    if (tid < BT) {
#pragma unroll
        for (int j = 0; j < 24; j++) s.XP[j][tid] = 0.f;
        s.XP[0][tid]  = hist[(size_t)(b0 + tid) * 40 + 0];
        s.XP[3][tid]  = hist[(size_t)(b0 + tid) * 40 + 1];
        s.XP[6][tid]  = rx; s.XP[10][tid] = vv; s.XP[14][tid] = aa;
        s.XP[15][tid] = rx; s.XP[19][tid] = vv; s.XP[23][tid] = aa;
    }

    float Creg[3][4];
#pragma unroll
    for (int l = 0; l < 3; l++)
#pragma unroll
        for (int j = 0; j < 4; j++) Creg[l][j] = 0.f;

    float D[3][4][4];
    __syncthreads();

    // initial h-part prefetch for layer 0
    mma_part(s, 0, 1, w0, lane, grp, D[0], true);

    // ================= encoder: t = 1..19 =================
    for (int t = 1; t < TH; t++) {
        input_layer(s, b, d0o);
        barg(grp);
        // S1
        mma_part(s, 0, 0, w0, lane, grp, D[0], false);
        mma_part(s, 1, 1, w0, lane, grp, D[1], true);
        epilogue(s, 0, w0, lane, grp, D[0], Creg[0]);
        barg(grp);
        // S2
        mma_part(s, 1, 0, w0, lane, grp, D[1], false);
        mma_part(s, 2, 1, w0, lane, grp, D[2], true);
        epilogue(s, 1, w0, lane, grp, D[1], Creg[1]);
        barg(grp);
        // S3
        mma_part(s, 2, 0, w0, lane, grp, D[2], false);
        if (t < TH - 1)
            mma_part(s, 0, 1, w0, lane, grp, D[0], true);   // next step's h(0)
        epilogue(s, 2, w0, lane, grp, D[2], Creg[2]);
        if (ltid < 32) {
            int bb2 = grp * 16 + (ltid & 15), f = ltid >> 4;
            int xo = f ? 3 : 0, po = f ? 15 : 6;
            float X[3], P[9];
#pragma unroll
            for (int i = 0; i < 3; i++) X[i] = s.XP[xo + i][bb2];
#pragma unroll
            for (int i = 0; i < 9; i++) P[i] = s.XP[po + i][bb2];
            if (f == 0) kpred_f(X, P, gxe0, gxe1, gxe2);
            else        kpred_f(X, P, gye0, gye1, gye2);
            kupd_f(X, P, s.Zs[f][t][bb2], f ? ry : rx);
#pragma unroll
            for (int i = 0; i < 3; i++) s.XP[xo + i][bb2] = X[i];
#pragma unroll
            for (int i = 0; i < 9; i++) s.XP[po + i][bb2] = P[i];
        }
        barg(grp);
    }

    // ---- swap in decoder weights (full CTA) ----
    __syncthreads();
    pack_wts(s, tid, dWih, dWhh, dbih, dbhh);
    __syncthreads();
    mma_part(s, 0, 1, w0, lane, grp, D[0], true);   // h(0) with decoder weights

    // ================= decoder: 30 steps =================
    for (int st = 0; st < LP; st++) {
        input_layer(s, b, d0o);
        barg(grp);
        mma_part(s, 0, 0, w0, lane, grp, D[0], false);
        mma_part(s, 1, 1, w0, lane, grp, D[1], true);
        epilogue(s, 0, w0, lane, grp, D[0], Creg[0]);
        barg(grp);
        mma_part(s, 1, 0, w0, lane, grp, D[1], false);
        mma_part(s, 2, 1, w0, lane, grp, D[2], true);
        epilogue(s, 1, w0, lane, grp, D[1], Creg[1]);
        barg(grp);
        mma_part(s, 2, 0, w0, lane, grp, D[2], false);
        if (st < LP - 1)
            mma_part(s, 0, 1, w0, lane, grp, D[0], true);
        epilogue(s, 2, w0, lane, grp, D[2], Creg[2]);
        barg(grp);
        // pred (inline) + Kalman
        if (ltid < 32) {
            int bb2 = grp * 16 + (ltid & 15), f = ltid >> 4;
            float a0 = s.Woutb[f], a1 = s.Woutb[2 + f];
#pragma unroll 8
            for (int k = 0; k < 32; k++) {
                float cv = s.c2f[bb2][k];
                a0 = fmaf(cv, s.WoutT[k][f], a0);
                a1 = fmaf(cv, s.WoutT[k][2 + f], a1);
            }
            int xo = f ? 3 : 0, po = f ? 15 : 6;
            float X[3], P[9];
#pragma unroll
            for (int i = 0; i < 3; i++) X[i] = s.XP[xo + i][bb2];
#pragma unroll
            for (int i = 0; i < 9; i++) P[i] = s.XP[po + i][bb2];
            X[2] = DTC * a0;
            float q0 = a1 * (f ? gy0 : gx0);
            float q1 = a1 * (f ? gy1 : gx1);
            float q2 = a1 * (f ? gy2 : gx2);
            kpred_f(X, P, q0, q1, q2);
#pragma unroll
            for (int i = 0; i < 3; i++) s.XP[xo + i][bb2] = X[i];
#pragma unroll
            for (int i = 0; i < 9; i++) s.XP[po + i][bb2] = P[i];
            float* o = out + (size_t)(b0 + bb2) * (LP * 5) + st * 5;
            if (f == 0) { o[0] = X[0]; o[2] = sqrtf(P[0]); }
            else        { o[1] = X[0]; o[3] = sqrtf(P[0]); o[4] = 0.0f; }
        }
        barg(grp);
    }
}

extern "C" void kernel_launch(void* const* d_in, const int* in_sizes, int n_in,
                              void* d_out, int out_size) {
    cudaFuncSetAttribute(kalman_lstm_kernel,
                         cudaFuncAttributeMaxDynamicSharedMemorySize,
                         (int)sizeof(SM));
    kalman_lstm_kernel<<<NCTA, NTHR, sizeof(SM)>>>(
        (const float*)d_in[0],  (const float*)d_in[1],  (const float*)d_in[2],
        (const float*)d_in[3],  (const float*)d_in[4],  (const float*)d_in[5],
        (const float*)d_in[6],  (const float*)d_in[7],  (const float*)d_in[8],
        (const float*)d_in[9],  (const float*)d_in[10], (const float*)d_in[11],
        (const float*)d_in[12], (const float*)d_in[13], (const float*)d_in[14],
        (const float*)d_in[15], (const float*)d_in[16], (const float*)d_in[17],
        (const float*)d_in[18], (const float*)d_in[19], (const float*)d_in[20],
        (float*)d_out);
}

// round 17
// speedup vs baseline: 1.3709x; 1.3709x over previous
#include <cuda_runtime.h>
#include <cuda_bf16.h>
#include <math.h>

typedef unsigned int u32;

#define BT   64
#define NCTA 128
#define NTHR 256
#define TH   20
#define LP   30
#define DTC  0.1f
#define D2C  0.005f
#define PADK 72     // bf16 per row in W/X tiles (conflict-free frag loads)
#define CPAD 33     // c2f row pad

struct __align__(16) SM {
    __nv_bfloat16 Wt[3][128 * PADK];     // [layer][m][k] k=[x32|h32], bf16 (hi only)
    __nv_bfloat16 Xt[3][2][64 * PADK];   // [layer][hi/lo][n][k] x cols 0-31, h cols 32-63
    float c2f[64][CPAD];                 // layer-2 c, [n][d]
    float XP[24][64];
    float Zs[2][TH][64];
    float bsum[3][128];
    float WinT[24][32];
    float Winb[32];
    float WoutT[32][4];
    float Woutb[4];
};

__device__ __forceinline__ void barg(int g) {
    asm volatile("bar.sync %0, %1;" :: "r"(g + 1), "r"(128) : "memory");
}
__device__ __forceinline__ float tanha(float x) {
    float y; asm("tanh.approx.f32 %0, %1;" : "=f"(y) : "f"(x)); return y;
}
__device__ __forceinline__ float sigm(float z) { return fmaf(tanha(0.5f * z), 0.5f, 0.5f); }
__device__ __forceinline__ u32 pkbf(float lo, float hi) {
    u32 r; asm("cvt.rn.bf16x2.f32 %0, %1, %2;" : "=r"(r) : "f"(hi), "f"(lo)); return r;
}
__device__ __forceinline__ void mma16816(float* d, const u32* a, u32 b0, u32 b1) {
    asm volatile("mma.sync.aligned.m16n8k16.row.col.f32.bf16.bf16.f32 "
        "{%0,%1,%2,%3}, {%4,%5,%6,%7}, {%8,%9}, {%0,%1,%2,%3};"
        : "+f"(d[0]), "+f"(d[1]), "+f"(d[2]), "+f"(d[3])
        : "r"(a[0]), "r"(a[1]), "r"(a[2]), "r"(a[3]), "r"(b0), "r"(b1));
}

__device__ __forceinline__ void pack_wts(SM& s, int tid,
        const float* __restrict__ Wih, const float* __restrict__ Whh,
        const float* __restrict__ bih, const float* __restrict__ bhh) {
    for (int i = tid; i < 3 * 128 * 64; i += NTHR) {
        int l = i >> 13, r = i & 8191, m = r >> 6, k = r & 63;
        float v = (k < 32) ? Wih[l * 4096 + m * 32 + k] : Whh[l * 4096 + m * 32 + (k - 32)];
        s.Wt[l][m * PADK + k] = __float2bfloat16(v);
    }
    for (int i = tid; i < 384; i += NTHR)
        ((float*)s.bsum)[i] = bih[i] + bhh[i];
}

__device__ __forceinline__ void kpred_f(float X[3], float P[9], float g0, float g1, float g2) {
    X[0] = X[0] + DTC * X[1] + D2C * X[2];
    X[1] = X[1] + DTC * X[2];
    float A[9];
#pragma unroll
    for (int j = 0; j < 3; j++) {
        A[0 * 3 + j] = P[0 * 3 + j] + DTC * P[1 * 3 + j] + D2C * P[2 * 3 + j];
        A[1 * 3 + j] = P[1 * 3 + j] + DTC * P[2 * 3 + j];
        A[2 * 3 + j] = P[2 * 3 + j];
    }
#pragma unroll
    for (int i = 0; i < 3; i++) {
        float qi = (i == 0) ? g0 : ((i == 1) ? g1 : g2);
        P[i * 3 + 0] = A[i * 3 + 0] + DTC * A[i * 3 + 1] + D2C * A[i * 3 + 2] + qi * g0;
        P[i * 3 + 1] = A[i * 3 + 1] + DTC * A[i * 3 + 2] + qi * g1;
        P[i * 3 + 2] = A[i * 3 + 2] + qi * g2;
    }
}
__device__ __forceinline__ void kupd_f(float X[3], float P[9], float z, float R) {
    float y = z - X[0];
    float S = P[0] + R;
    float inv = 1.0f / S;
    float K0 = P[0] * inv, K1 = P[3] * inv, K2 = P[6] * inv;
    X[0] += y * K0; X[1] += y * K1; X[2] += y * K2;
    float r0 = P[0], r1 = P[1], r2 = P[2];
    P[0] -= K0 * r0; P[1] -= K0 * r1; P[2] -= K0 * r2;
    P[3] -= K1 * r0; P[4] -= K1 * r1; P[5] -= K1 * r2;
    P[6] -= K2 * r0; P[7] -= K2 * r1; P[8] -= K2 * r2;
}

// input layer: x[b][d0..d0+7] = tanh(XP[.][b] @ Win^T + b) -> Xt[0] hi/lo x-cols
__device__ __forceinline__ void input_layer(SM& s, int b, int d0) {
    float acc[8];
    *(float4*)&acc[0] = *(const float4*)&s.Winb[d0];
    *(float4*)&acc[4] = *(const float4*)&s.Winb[d0 + 4];
#pragma unroll
    for (int k = 0; k < 24; k++) {
        float xv = s.XP[k][b];
        float4 w0 = *(const float4*)&s.WinT[k][d0];
        float4 w1 = *(const float4*)&s.WinT[k][d0 + 4];
        acc[0] = fmaf(w0.x, xv, acc[0]); acc[1] = fmaf(w0.y, xv, acc[1]);
        acc[2] = fmaf(w0.z, xv, acc[2]); acc[3] = fmaf(w0.w, xv, acc[3]);
        acc[4] = fmaf(w1.x, xv, acc[4]); acc[5] = fmaf(w1.y, xv, acc[5]);
        acc[6] = fmaf(w1.z, xv, acc[6]); acc[7] = fmaf(w1.w, xv, acc[7]);
    }
    float xh[8], xl[8];
#pragma unroll
    for (int j = 0; j < 8; j++) {
        float x = tanha(acc[j]);
        float h = __bfloat162float(__float2bfloat16(x));
        xh[j] = h; xl[j] = x - h;
    }
    uint4 qh, ql;
    qh.x = pkbf(xh[0], xh[1]); qh.y = pkbf(xh[2], xh[3]);
    qh.z = pkbf(xh[4], xh[5]); qh.w = pkbf(xh[6], xh[7]);
    ql.x = pkbf(xl[0], xl[1]); ql.y = pkbf(xl[2], xl[3]);
    ql.z = pkbf(xl[4], xl[5]); ql.w = pkbf(xl[6], xl[7]);
    *(uint4*)&s.Xt[0][0][b * PADK + d0] = qh;
    *(uint4*)&s.Xt[0][1][b * PADK + d0] = ql;
}

// half-K GEMM into D[gi][nt][4], 2-term: Wh*Xh + Wh*Xl (W bf16, X hi/lo).
__device__ __forceinline__ void mma_part(SM& s, int l, int kh, int w0, int lane, int grp,
                                         float (&D)[4][2][4], bool zero)
{
    const int g8 = lane >> 2, tg = lane & 3;
    const int d0 = (w0 & 1) * 16;
    const int nb = grp * 32 + (w0 >> 1) * 16;
    if (zero) {
#pragma unroll
        for (int gi = 0; gi < 4; gi++)
#pragma unroll
            for (int nt = 0; nt < 2; nt++)
#pragma unroll
                for (int j = 0; j < 4; j++) D[gi][nt][j] = 0.f;
    }
    const __nv_bfloat16* __restrict__ W0 = &s.Wt[l][0];
    const __nv_bfloat16* __restrict__ X0 = &s.Xt[l][0][0];
    const __nv_bfloat16* __restrict__ X1 = &s.Xt[l][1][0];
#pragma unroll
    for (int kk = 0; kk < 2; kk++) {
        const int k0 = (kh * 2 + kk) * 16 + 2 * tg;
        u32 ah[4][4];
#pragma unroll
        for (int gi = 0; gi < 4; gi++) {
            const int m = gi * 32 + d0 + g8;
            ah[gi][0] = *(const u32*)&W0[m * PADK + k0];
            ah[gi][1] = *(const u32*)&W0[(m + 8) * PADK + k0];
            ah[gi][2] = *(const u32*)&W0[m * PADK + k0 + 8];
            ah[gi][3] = *(const u32*)&W0[(m + 8) * PADK + k0 + 8];
        }
#pragma unroll
        for (int nt = 0; nt < 2; nt++) {
            const int n = nb + nt * 8 + g8;
            u32 bh0 = *(const u32*)&X0[n * PADK + k0];
            u32 bh1 = *(const u32*)&X0[n * PADK + k0 + 8];
            u32 bl0 = *(const u32*)&X1[n * PADK + k0];
            u32 bl1 = *(const u32*)&X1[n * PADK + k0 + 8];
#pragma unroll
            for (int gi = 0; gi < 4; gi++) {
                mma16816(D[gi][nt], ah[gi], bh0, bh1);
                mma16816(D[gi][nt], ah[gi], bl0, bl1);
            }
        }
    }
}

// in-register epilogue: gates in D -> c,h -> bf16 hi/lo tiles (+ c2f for l==2)
__device__ __forceinline__ void epilogue(SM& s, int l, int w0, int lane, int grp,
                                         float (&D)[4][2][4], float* C)
{
    const int g8 = lane >> 2, tg = lane & 3;
    const int d0 = (w0 & 1) * 16;
    const int nb = grp * 32 + (w0 >> 1) * 16;
    const float* bb = &s.bsum[l][0];
    __nv_bfloat16* __restrict__ H0 = &s.Xt[l][0][0];
    __nv_bfloat16* __restrict__ H1 = &s.Xt[l][1][0];
#pragma unroll
    for (int dd = 0; dd < 2; dd++) {
        const int d = d0 + g8 + dd * 8;
        const float bi = bb[d], bf_ = bb[32 + d], bg = bb[64 + d], bo = bb[96 + d];
#pragma unroll
        for (int nt = 0; nt < 2; nt++) {
#pragma unroll
            for (int dn = 0; dn < 2; dn++) {
                const int j = dn + dd * 2;
                const int n = nb + nt * 8 + 2 * tg + dn;
                const int ci = dd * 4 + nt * 2 + dn;
                float c = fmaf(sigm(D[1][nt][j] + bf_), C[ci],
                               sigm(D[0][nt][j] + bi) * tanha(D[2][nt][j] + bg));
                float h = sigm(D[3][nt][j] + bo) * tanha(c);
                C[ci] = c;
                __nv_bfloat16 hh = __float2bfloat16(h);
                H0[n * PADK + 32 + d] = hh;
                H1[n * PADK + 32 + d] = __float2bfloat16(h - __bfloat162float(hh));
                if (l < 2) {
                    __nv_bfloat16 ch = __float2bfloat16(c);
                    s.Xt[l + 1][0][n * PADK + d] = ch;
                    s.Xt[l + 1][1][n * PADK + d] = __float2bfloat16(c - __bfloat162float(ch));
                } else {
                    s.c2f[n][d] = c;
                }
            }
        }
    }
}

__global__ void __launch_bounds__(NTHR, 1)
kalman_lstm_kernel(const float* __restrict__ hist,
                   const float* __restrict__ mx,  const float* __restrict__ my,
                   const float* __restrict__ vsx, const float* __restrict__ asx,
                   const float* __restrict__ Rxp, const float* __restrict__ Ryp,
                   const float* __restrict__ Gx,  const float* __restrict__ Gy,
                   const float* __restrict__ WinW, const float* __restrict__ Winb,
                   const float* __restrict__ eWih, const float* __restrict__ eWhh,
                   const float* __restrict__ ebih, const float* __restrict__ ebhh,
                   const float* __restrict__ dWih, const float* __restrict__ dWhh,
                   const float* __restrict__ dbih, const float* __restrict__ dbhh,
                   const float* __restrict__ WoutW, const float* __restrict__ Woutb,
                   float* __restrict__ out)
{
    extern __shared__ char smraw[];
    SM& s = *reinterpret_cast<SM*>(smraw);
    const int tid  = threadIdx.x;
    const int wid  = tid >> 5, lane = tid & 31;
    const int b0   = blockIdx.x * BT;
    const int grp  = wid >> 2;
    const int w0   = wid & 3;
    const int ltid = tid & 127;
    const int b    = grp * 32 + (ltid & 31);
    const int d0o  = (ltid >> 5) * 8;

    // ---- one-time setup (full CTA) ----
    pack_wts(s, tid, eWih, eWhh, ebih, ebhh);
    for (int i = tid; i < 24 * 32; i += NTHR) {
        int d = i & 31, k = i >> 5;
        s.WinT[k][d] = WinW[d * 24 + k];
    }
    if (tid < 32) s.Winb[tid] = Winb[tid];
    if (tid < 128) { int k = tid >> 2, qq = tid & 3; s.WoutT[k][qq] = WoutW[qq * 32 + k]; }
    if (tid < 4)  s.Woutb[tid] = Woutb[tid];
    for (int i = tid; i < BT * 40; i += NTHR) {
        int bb2 = i / 40, j = i % 40;
        s.Zs[j & 1][j >> 1][bb2] = hist[(size_t)(b0 + bb2) * 40 + j];
    }
    for (int i = tid; i < (int)(sizeof(s.Xt) / 4); i += NTHR)
        ((u32*)&s.Xt[0][0][0])[i] = 0u;

    const float rx = Rxp[0] * Rxp[0], ry = Ryp[0] * Ryp[0];
    const float vv = vsx[0] * vsx[0], aa = asx[0] * asx[0];
    const float gxe0 = Gx[0] * mx[0], gxe1 = Gx[1] * mx[0], gxe2 = Gx[2] * mx[0];
    const float gye0 = Gy[0] * my[0], gye1 = Gy[1] * my[0], gye2 = Gy[2] * my[0];
    const float gx0 = Gx[0], gx1 = Gx[1], gx2 = Gx[2];
    const float gy0 = Gy[0], gy1 = Gy[1], gy2 = Gy[2];

    if (tid < BT) {
#pragma unroll
        for (int j = 0; j < 24; j++) s.XP[j][tid] = 0.f;
        s.XP[0][tid]  = hist[(size_t)(b0 + tid) * 40 + 0];
        s.XP[3][tid]  = hist[(size_t)(b0 + tid) * 40 + 1];
        s.XP[6][tid]  = rx; s.XP[10][tid] = vv; s.XP[14][tid] = aa;
        s.XP[15][tid] = rx; s.XP[19][tid] = vv; s.XP[23][tid] = aa;
    }

    float Creg[3][8];
#pragma unroll
    for (int l = 0; l < 3; l++)
#pragma unroll
        for (int j = 0; j < 8; j++) Creg[l][j] = 0.f;

    float D[3][4][2][4];
    __syncthreads();

    // initial h-part prefetch for layer 0
    mma_part(s, 0, 1, w0, lane, grp, D[0], true);

    // ================= encoder: t = 1..19 =================
    for (int t = 1; t < TH; t++) {
        input_layer(s, b, d0o);
        barg(grp);
        // S1
        mma_part(s, 0, 0, w0, lane, grp, D[0], false);
        mma_part(s, 1, 1, w0, lane, grp, D[1], true);
        epilogue(s, 0, w0, lane, grp, D[0], Creg[0]);
        barg(grp);
        // S2
        mma_part(s, 1, 0, w0, lane, grp, D[1], false);
        mma_part(s, 2, 1, w0, lane, grp, D[2], true);
        epilogue(s, 1, w0, lane, grp, D[1], Creg[1]);
        barg(grp);
        // S3
        mma_part(s, 2, 0, w0, lane, grp, D[2], false);
        if (t < TH - 1)
            mma_part(s, 0, 1, w0, lane, grp, D[0], true);   // next step's h(0)
        epilogue(s, 2, w0, lane, grp, D[2], Creg[2]);
        if (ltid < 64) {
            int bb2 = grp * 32 + (ltid & 31), f = ltid >> 5;
            int xo = f ? 3 : 0, po = f ? 15 : 6;
            float X[3], P[9];
#pragma unroll
            for (int i = 0; i < 3; i++) X[i] = s.XP[xo + i][bb2];
#pragma unroll
            for (int i = 0; i < 9; i++) P[i] = s.XP[po + i][bb2];
            if (f == 0) kpred_f(X, P, gxe0, gxe1, gxe2);
            else        kpred_f(X, P, gye0, gye1, gye2);
            kupd_f(X, P, s.Zs[f][t][bb2], f ? ry : rx);
#pragma unroll
            for (int i = 0; i < 3; i++) s.XP[xo + i][bb2] = X[i];
#pragma unroll
            for (int i = 0; i < 9; i++) s.XP[po + i][bb2] = P[i];
        }
        barg(grp);
    }

    // ---- swap in decoder weights (full CTA) ----
    __syncthreads();
    pack_wts(s, tid, dWih, dWhh, dbih, dbhh);
    __syncthreads();
    mma_part(s, 0, 1, w0, lane, grp, D[0], true);   // h(0) with decoder weights

    // ================= decoder: 30 steps =================
    for (int st = 0; st < LP; st++) {
        input_layer(s, b, d0o);
        barg(grp);
        mma_part(s, 0, 0, w0, lane, grp, D[0], false);
        mma_part(s, 1, 1, w0, lane, grp, D[1], true);
        epilogue(s, 0, w0, lane, grp, D[0], Creg[0]);
        barg(grp);
        mma_part(s, 1, 0, w0, lane, grp, D[1], false);
        mma_part(s, 2, 1, w0, lane, grp, D[2], true);
        epilogue(s, 1, w0, lane, grp, D[1], Creg[1]);
        barg(grp);
        mma_part(s, 2, 0, w0, lane, grp, D[2], false);
        if (st < LP - 1)
            mma_part(s, 0, 1, w0, lane, grp, D[0], true);
        epilogue(s, 2, w0, lane, grp, D[2], Creg[2]);
        barg(grp);
        // pred (inline) + Kalman
        if (ltid < 64) {
            int bb2 = grp * 32 + (ltid & 31), f = ltid >> 5;
            float a0 = s.Woutb[f], a1 = s.Woutb[2 + f];
#pragma unroll 8
            for (int k = 0; k < 32; k++) {
                float cv = s.c2f[bb2][k];
                a0 = fmaf(cv, s.WoutT[k][f], a0);
                a1 = fmaf(cv, s.WoutT[k][2 + f], a1);
            }
            int xo = f ? 3 : 0, po = f ? 15 : 6;
            float X[3], P[9];
#pragma unroll
            for (int i = 0; i < 3; i++) X[i] = s.XP[xo + i][bb2];
#pragma unroll
            for (int i = 0; i < 9; i++) P[i] = s.XP[po + i][bb2];
            X[2] = DTC * a0;
            float q0 = a1 * (f ? gy0 : gx0);
            float q1 = a1 * (f ? gy1 : gx1);
            float q2 = a1 * (f ? gy2 : gx2);
            kpred_f(X, P, q0, q1, q2);
#pragma unroll
            for (int i = 0; i < 3; i++) s.XP[xo + i][bb2] = X[i];
#pragma unroll
            for (int i = 0; i < 9; i++) s.XP[po + i][bb2] = P[i];
            float* o = out + (size_t)(b0 + bb2) * (LP * 5) + st * 5;
            if (f == 0) { o[0] = X[0]; o[2] = sqrtf(P[0]); }
            else        { o[1] = X[0]; o[3] = sqrtf(P[0]); o[4] = 0.0f; }
        }
        barg(grp);
    }
}

extern "C" void kernel_launch(void* const* d_in, const int* in_sizes, int n_in,
                              void* d_out, int out_size) {
    cudaFuncSetAttribute(kalman_lstm_kernel,
                         cudaFuncAttributeMaxDynamicSharedMemorySize,
                         (int)sizeof(SM));
    kalman_lstm_kernel<<<NCTA, NTHR, sizeof(SM)>>>(
        (const float*)d_in[0],  (const float*)d_in[1],  (const float*)d_in[2],
        (const float*)d_in[3],  (const float*)d_in[4],  (const float*)d_in[5],
        (const float*)d_in[6],  (const float*)d_in[7],  (const float*)d_in[8],
        (const float*)d_in[9],  (const float*)d_in[10], (const float*)d_in[11],
        (const float*)d_in[12], (const float*)d_in[13], (const float*)d_in[14],
        (const float*)d_in[15], (const float*)d_in[16], (const float*)d_in[17],
        (const float*)d_in[18], (const float*)d_in[19], (const float*)d_in[20],
        (float*)d_out);
}